// round 7
// baseline (speedup 1.0000x reference)
#include <cuda_runtime.h>

#define BQ     2048
#define IND    512
#define OUTD   512
#define NEXP   64

#define BM     16
#define BN     128
#define BK     32
#define NT     64            // 2 warps
#define NTILES (OUTD / BN)   // 4
#define NSTAGE (IND / BK)    // 16
#define GRID_GEMM 768        // worst case: (64 + 2048/16) chunks * 4 tiles = 768
#define MAXITEMS 1024

__device__ int g_count[NEXP];
__device__ int g_list[NEXP * BQ];
__device__ int g_items[MAXITEMS];
__device__ int g_nitems;

// ---------------- prep ----------------
__global__ void prep_kernel(const int* __restrict__ ids) {
    __shared__ int sc[NEXP];
    int t = threadIdx.x;
    if (t < NEXP) sc[t] = 0;
    __syncthreads();
    for (int i = t; i < BQ; i += blockDim.x) {
        int e = ids[i];
        if ((unsigned)e < NEXP) {
            int p = atomicAdd(&sc[e], 1);
            g_list[e * BQ + p] = i;
        }
    }
    __syncthreads();
    if (t < NEXP) g_count[t] = sc[t];
    if (t == 0) {
        int ni = 0;
        for (int e = 0; e < NEXP; e++) {
            int n = sc[e];
            for (int c = 0; c * BM < n && ni <= MAXITEMS - NTILES; c++)
                for (int tl = 0; tl < NTILES; tl++)
                    g_items[ni++] = (e << 16) | (c << 2) | tl;
        }
        g_nitems = ni;
    }
}

// ---------------- packed fp32 helpers ----------------
__device__ __forceinline__ unsigned long long dup_f32(float v) {
    unsigned long long r;
    unsigned int u = __float_as_uint(v);
    asm("mov.b64 %0, {%1, %1};" : "=l"(r) : "r"(u));
    return r;
}
__device__ __forceinline__ void fma2(unsigned long long& d,
                                     unsigned long long a,
                                     unsigned long long b) {
    asm("fma.rn.f32x2 %0, %1, %2, %0;" : "+l"(d) : "l"(a), "l"(b));
}

// ---------------- grouped GEMM, software-pipelined ----------------
// Item = (expert, 16-sample chunk, 128-out tile); uniform cost -> static map.
// 64 threads; thread (mg = t&1, cgrp = t>>1) owns rows mg*8..+7, cols cgrp*4..+3.
__global__ __launch_bounds__(NT) void gemm_kernel(
    const float* __restrict__ x,
    const float* __restrict__ w,
    float* __restrict__ out)
{
    __shared__ float ws[2][BK][BN];               // 2 x 16 KB, [k][n]
    __shared__ unsigned long long xs[2][BK][BM];  // 2 x 4 KB, dup-packed, [k][m]
    __shared__ int sidx[BM];

    const int it = blockIdx.x;
    if (it >= g_nitems) return;

    const int t    = threadIdx.x;
    const int mg   = t & 1;
    const int cgrp = t >> 1;

    const int pk   = g_items[it];
    const int e    = pk >> 16;
    const int tile = pk & 3;
    const int m0   = ((pk >> 2) & 0x3fff) * BM;
    const int n    = g_count[e];
    const int* ls  = g_list + e * BQ;

    if (t < BM) { int m = m0 + t; sidx[t] = ls[m < n ? m : 0]; }
    __syncthreads();

    const float* wb = w + ((size_t)e * OUTD + (size_t)tile * BN) * IND;
    // x-fill mapping: per half h, f = t + 64h -> row m = f>>3, float4 q = f&7
    const int xm0 = t >> 3;
    const int xq0 = t & 7;
    const int xm1 = (t + 64) >> 3;
    const int xq1 = (t + 64) & 7;
    const float* xrow0 = x + (size_t)sidx[xm0] * IND + xq0 * 4;
    const float* xrow1 = x + (size_t)sidx[xm1] * IND + xq1 * 4;

    unsigned long long acc[8][2];
    #pragma unroll
    for (int r = 0; r < 8; r++) { acc[r][0] = 0ULL; acc[r][1] = 0ULL; }

    float4 rw[2][8];   // W rows t and t+64, 32 k-floats each
    float4 rx[2];      // two x float4s

    // ---- prefetch stage 0
    {
        const float4* s0 = (const float4*)(wb + (size_t)t * IND);
        const float4* s1 = (const float4*)(wb + (size_t)(t + 64) * IND);
        #pragma unroll
        for (int j = 0; j < 8; j++) { rw[0][j] = s0[j]; rw[1][j] = s1[j]; }
        rx[0] = *(const float4*)(xrow0);
        rx[1] = *(const float4*)(xrow1);
    }

    for (int s = 0; s < NSTAGE; s++) {
        const int b = s & 1;
        float (*wsb)[BN] = ws[b];
        unsigned long long (*xsb)[BM] = xs[b];

        // ---- STS stage s (transpose W, dup-pack x)
        #pragma unroll
        for (int h = 0; h < 2; h++) {
            int nr = t + 64 * h;
            #pragma unroll
            for (int j = 0; j < 8; j++) {
                float4 v = rw[h][j];
                int k = j * 4;
                wsb[k + 0][nr] = v.x;
                wsb[k + 1][nr] = v.y;
                wsb[k + 2][nr] = v.z;
                wsb[k + 3][nr] = v.w;
            }
        }
        {
            int k0q = xq0 * 4;
            xsb[k0q + 0][xm0] = dup_f32(rx[0].x);
            xsb[k0q + 1][xm0] = dup_f32(rx[0].y);
            xsb[k0q + 2][xm0] = dup_f32(rx[0].z);
            xsb[k0q + 3][xm0] = dup_f32(rx[0].w);
            int k1q = xq1 * 4;
            xsb[k1q + 0][xm1] = dup_f32(rx[1].x);
            xsb[k1q + 1][xm1] = dup_f32(rx[1].y);
            xsb[k1q + 2][xm1] = dup_f32(rx[1].z);
            xsb[k1q + 3][xm1] = dup_f32(rx[1].w);
        }
        __syncthreads();   // stage s visible; prior compute (s-1, other buf) done

        // ---- prefetch stage s+1 (overlaps compute below)
        if (s + 1 < NSTAGE) {
            int k0 = (s + 1) * BK;
            const float4* s0 = (const float4*)(wb + (size_t)t * IND + k0);
            const float4* s1 = (const float4*)(wb + (size_t)(t + 64) * IND + k0);
            #pragma unroll
            for (int j = 0; j < 8; j++) { rw[0][j] = s0[j]; rw[1][j] = s1[j]; }
            rx[0] = *(const float4*)(xrow0 + k0);
            rx[1] = *(const float4*)(xrow1 + k0);
        }

        // ---- compute stage s
        #pragma unroll 4
        for (int kk = 0; kk < BK; kk++) {
            const ulonglong2* xr = (const ulonglong2*)&xsb[kk][mg * 8];
            ulonglong2 a01 = xr[0];
            ulonglong2 a23 = xr[1];
            ulonglong2 a45 = xr[2];
            ulonglong2 a67 = xr[3];
            ulonglong2 bq  = *(const ulonglong2*)&wsb[kk][cgrp * 4];

            unsigned long long av[8] = {a01.x, a01.y, a23.x, a23.y,
                                        a45.x, a45.y, a67.x, a67.y};
            #pragma unroll
            for (int r = 0; r < 8; r++) {
                fma2(acc[r][0], av[r], bq.x);
                fma2(acc[r][1], av[r], bq.y);
            }
        }
    }

    // ---- store 8 rows x 4 cols (rows masked)
    #pragma unroll
    for (int r = 0; r < 8; r++) {
        int m = m0 + mg * 8 + r;
        if (m < n) {
            float* op = out + (size_t)sidx[mg * 8 + r] * OUTD + tile * BN + cgrp * 4;
            float4 o;
            o.x = __uint_as_float((unsigned)(acc[r][0]));
            o.y = __uint_as_float((unsigned)(acc[r][0] >> 32));
            o.z = __uint_as_float((unsigned)(acc[r][1]));
            o.w = __uint_as_float((unsigned)(acc[r][1] >> 32));
            *(float4*)op = o;
        }
    }
}

extern "C" void kernel_launch(void* const* d_in, const int* in_sizes, int n_in,
                              void* d_out, int out_size) {
    const float* x = nullptr;
    const int* ids = nullptr;
    const float* w = nullptr;
    for (int i = 0; i < n_in; i++) {
        if (in_sizes[i] == BQ * IND)                x   = (const float*)d_in[i];
        else if (in_sizes[i] == BQ)                 ids = (const int*)d_in[i];
        else if (in_sizes[i] == NEXP * OUTD * IND)  w   = (const float*)d_in[i];
    }
    float* out = (float*)d_out;

    prep_kernel<<<1, 256>>>(ids);
    gemm_kernel<<<GRID_GEMM, NT>>>(x, w, out);
}

// round 8
// speedup vs baseline: 1.9035x; 1.9035x over previous
#include <cuda_runtime.h>

#define BQ     2048
#define IND    512
#define OUTD   512
#define NEXP   64

#define BM     32
#define BN     128
#define BK     32
#define NT     128
#define NTILES (OUTD / BN)   // 4
#define NSTAGE (IND / BK)    // 16
#define WPITCH 36            // floats per W smem row (32 + 4 pad, 144B, 16B-aligned)
#define XPITCH 36
#define GRID_GEMM 512        // worst case: 128 chunks * 4 tiles
#define MAXITEMS 768

__device__ int g_count[NEXP];
__device__ int g_list[NEXP * BQ];
__device__ int g_items[MAXITEMS];
__device__ int g_nitems;

// ---------------- prep ----------------
__global__ void prep_kernel(const int* __restrict__ ids) {
    __shared__ int sc[NEXP];
    int t = threadIdx.x;
    if (t < NEXP) sc[t] = 0;
    __syncthreads();
    for (int i = t; i < BQ; i += blockDim.x) {
        int e = ids[i];
        if ((unsigned)e < NEXP) {
            int p = atomicAdd(&sc[e], 1);
            g_list[e * BQ + p] = i;
        }
    }
    __syncthreads();
    if (t < NEXP) g_count[t] = sc[t];
    if (t == 0) {
        int ni = 0;
        for (int e = 0; e < NEXP; e++) {
            int n = sc[e];
            for (int c = 0; c * BM < n && ni <= MAXITEMS - NTILES; c++)
                for (int tl = 0; tl < NTILES; tl++)
                    g_items[ni++] = (e << 16) | (c << 2) | tl;
        }
        g_nitems = ni;
    }
}

// ---------------- helpers ----------------
__device__ __forceinline__ void fma2(unsigned long long& d,
                                     unsigned long long a,
                                     unsigned long long b) {
    asm("fma.rn.f32x2 %0, %1, %2, %0;" : "+l"(d) : "l"(a), "l"(b));
}
__device__ __forceinline__ unsigned sm_addr(const void* p) {
    return (unsigned)__cvta_generic_to_shared(p);
}
__device__ __forceinline__ void cp16(unsigned dst, const void* src) {
    asm volatile("cp.async.cg.shared.global [%0], [%1], 16;\n" :: "r"(dst), "l"(src));
}
#define CP_COMMIT() asm volatile("cp.async.commit_group;\n" ::: "memory")
#define CP_WAIT1()  asm volatile("cp.async.wait_group 1;\n" ::: "memory")
#define CP_WAIT0()  asm volatile("cp.async.wait_group 0;\n" ::: "memory")

// ---------------- grouped GEMM, k-major smem + split-K-in-lanes f32x2 ----------------
// Item = (expert, 32-sample chunk, 128-out tile); uniform cost -> static map.
// 128 threads: mg = t&3 -> rows {mg, mg+4, ..., mg+28}; cg = t>>2 -> cols {cg, cg+32, cg+64, cg+96}.
// acc[r][c] is a packed f32x2: lo = even-k partial sum, hi = odd-k partial sum.
__global__ __launch_bounds__(NT, 4) void gemm_kernel(
    const float* __restrict__ x,
    const float* __restrict__ w,
    float* __restrict__ out)
{
    __shared__ float ws[2][BN * WPITCH];   // 2 x 18 KB, k-major per out-row
    __shared__ float xs[2][BM * XPITCH];   // 2 x 4.5 KB, k-major per sample
    __shared__ int sidx[BM];

    const int it = blockIdx.x;
    if (it >= g_nitems) return;

    const int t  = threadIdx.x;
    const int mg = t & 3;
    const int cg = t >> 2;

    const int pk   = g_items[it];
    const int e    = pk >> 16;
    const int tile = pk & 3;
    const int m0   = ((pk >> 2) & 0x3fff) * BM;
    const int n    = g_count[e];
    const int* ls  = g_list + e * BQ;

    if (t < BM) {
        int m = m0 + t;
        sidx[t] = ls[m < n ? m : n - 1];   // clamp: duplicate work, masked at store
    }
    __syncthreads();

    const float* wb = w + ((size_t)e * OUTD + (size_t)tile * BN) * IND;

    // fill mappings (coalesced: consecutive lanes -> consecutive 16B)
    const int wrow = t >> 3;            // + 16*p
    const int wq4  = (t & 7) * 4;
    const int xm0  = t >> 3;            // x half 0
    const int xq0  = (t & 7) * 4;
    const int xm1  = (t + NT) >> 3;     // x half 1
    const int xq1  = ((t + NT) & 7) * 4;
    const float* xr0 = x + (size_t)sidx[xm0] * IND + xq0;
    const float* xr1 = x + (size_t)sidx[xm1] * IND + xq1;

    unsigned long long acc[8][4];
    #pragma unroll
    for (int r = 0; r < 8; r++)
        #pragma unroll
        for (int c = 0; c < 4; c++) acc[r][c] = 0ULL;

    // ---- prologue: stage 0
    {
        float* wsb = ws[0];
        float* xsb = xs[0];
        #pragma unroll
        for (int p = 0; p < 8; p++) {
            int row = wrow + 16 * p;
            cp16(sm_addr(&wsb[row * WPITCH + wq4]), wb + (size_t)row * IND + wq4);
        }
        cp16(sm_addr(&xsb[xm0 * XPITCH + xq0]), xr0);
        cp16(sm_addr(&xsb[xm1 * XPITCH + xq1]), xr1);
        CP_COMMIT();
    }

    for (int s = 0; s < NSTAGE; s++) {
        // ---- issue stage s+1 (other buffer, safe: barrier at loop end of s-1)
        if (s + 1 < NSTAGE) {
            int k0 = (s + 1) * BK;
            float* wsb = ws[(s + 1) & 1];
            float* xsb = xs[(s + 1) & 1];
            #pragma unroll
            for (int p = 0; p < 8; p++) {
                int row = wrow + 16 * p;
                cp16(sm_addr(&wsb[row * WPITCH + wq4]), wb + (size_t)row * IND + k0 + wq4);
            }
            cp16(sm_addr(&xsb[xm0 * XPITCH + xq0]), xr0 + k0);
            cp16(sm_addr(&xsb[xm1 * XPITCH + xq1]), xr1 + k0);
            CP_COMMIT();
            CP_WAIT1();     // stage s complete
        } else {
            CP_WAIT0();
        }
        __syncthreads();    // stage s visible to all warps

        // ---- compute stage s
        const float* wsb = ws[s & 1];
        const float* xsb = xs[s & 1];
        #pragma unroll
        for (int kp = 0; kp < BK / 4; kp++) {
            ulonglong2 wv[4];
            #pragma unroll
            for (int c = 0; c < 4; c++)
                wv[c] = *(const ulonglong2*)&wsb[(cg + 32 * c) * WPITCH + kp * 4];
            #pragma unroll
            for (int r = 0; r < 8; r++) {
                ulonglong2 xv = *(const ulonglong2*)&xsb[(mg + 4 * r) * XPITCH + kp * 4];
                #pragma unroll
                for (int c = 0; c < 4; c++) {
                    fma2(acc[r][c], xv.x, wv[c].x);
                    fma2(acc[r][c], xv.y, wv[c].y);
                }
            }
        }
        __syncthreads();    // all warps done reading buf s before it is refilled
    }

    // ---- store: rows mg+4r (masked), cols tile*BN + cg + 32c; merge k-halves
    #pragma unroll
    for (int r = 0; r < 8; r++) {
        int ml = mg + 4 * r;
        int m  = m0 + ml;
        if (m < n) {
            float* op = out + (size_t)sidx[ml] * OUTD + (size_t)tile * BN + cg;
            #pragma unroll
            for (int c = 0; c < 4; c++) {
                float lo = __uint_as_float((unsigned)(acc[r][c]));
                float hi = __uint_as_float((unsigned)(acc[r][c] >> 32));
                op[32 * c] = lo + hi;
            }
        }
    }
}

extern "C" void kernel_launch(void* const* d_in, const int* in_sizes, int n_in,
                              void* d_out, int out_size) {
    const float* x = nullptr;
    const int* ids = nullptr;
    const float* w = nullptr;
    for (int i = 0; i < n_in; i++) {
        if (in_sizes[i] == BQ * IND)                x   = (const float*)d_in[i];
        else if (in_sizes[i] == BQ)                 ids = (const int*)d_in[i];
        else if (in_sizes[i] == NEXP * OUTD * IND)  w   = (const float*)d_in[i];
    }
    float* out = (float*)d_out;

    prep_kernel<<<1, 256>>>(ids);
    gemm_kernel<<<GRID_GEMM, NT>>>(x, w, out);
}

// round 9
// speedup vs baseline: 1.9379x; 1.0181x over previous
#include <cuda_runtime.h>

#define BQ     2048
#define IND    512
#define OUTD   512
#define NEXP   64

#define BM     32
#define BN     128
#define BK     32
#define NT     128
#define NTILES (OUTD / BN)   // 4
#define NSTAGE (IND / BK)    // 16
#define WPITCH 36
#define XPITCH 36
#define GRID_GEMM 512
#define MAXITEMS 768

__device__ int g_count[NEXP];
__device__ int g_list[NEXP * BQ];
__device__ int g_items[MAXITEMS];
__device__ int g_nitems;

// ---------------- prep: mixed 32/16-row chunks ----------------
// pk = (e<<16) | (m016<<4) | (small<<2) | tile
__global__ void prep_kernel(const int* __restrict__ ids) {
    __shared__ int sc[NEXP];
    int t = threadIdx.x;
    if (t < NEXP) sc[t] = 0;
    __syncthreads();
    for (int i = t; i < BQ; i += blockDim.x) {
        int e = ids[i];
        if ((unsigned)e < NEXP) {
            int p = atomicAdd(&sc[e], 1);
            g_list[e * BQ + p] = i;
        }
    }
    __syncthreads();
    if (t < NEXP) g_count[t] = sc[t];
    if (t == 0) {
        int ni = 0;
        for (int e = 0; e < NEXP; e++) {
            int n = sc[e];
            int nf = n >> 5;               // full 32-row chunks
            int rem = n - (nf << 5);
            for (int c = 0; c < nf && ni <= MAXITEMS - NTILES; c++)
                for (int tl = 0; tl < NTILES; tl++)
                    g_items[ni++] = (e << 16) | ((c * 2) << 4) | tl;
            if (rem > 0 && ni <= MAXITEMS - NTILES) {
                int small = (rem <= 16) ? 1 : 0;
                for (int tl = 0; tl < NTILES; tl++)
                    g_items[ni++] = (e << 16) | ((nf * 2) << 4) | (small << 2) | tl;
            }
        }
        g_nitems = ni;
    }
}

// ---------------- helpers ----------------
__device__ __forceinline__ void fma2(unsigned long long& d,
                                     unsigned long long a,
                                     unsigned long long b) {
    asm("fma.rn.f32x2 %0, %1, %2, %0;" : "+l"(d) : "l"(a), "l"(b));
}
__device__ __forceinline__ unsigned sm_addr(const void* p) {
    return (unsigned)__cvta_generic_to_shared(p);
}
__device__ __forceinline__ void cp16(unsigned dst, const void* src) {
    asm volatile("cp.async.cg.shared.global [%0], [%1], 16;\n" :: "r"(dst), "l"(src));
}
#define CP_COMMIT() asm volatile("cp.async.commit_group;\n" ::: "memory")
#define CP_WAIT1()  asm volatile("cp.async.wait_group 1;\n" ::: "memory")
#define CP_WAIT0()  asm volatile("cp.async.wait_group 0;\n" ::: "memory")

// ---------------- templated item body ----------------
// RMAX=8 -> 32 rows, RMAX=4 -> 16 rows. Thread (mg=t&3, cg=t>>2) owns
// rows {mg+4r}, cols {cg+32c}. acc f32x2: lo=even-k sum, hi=odd-k sum.
template <int RMAX>
__device__ __forceinline__ void run_item(
    const float* __restrict__ x, const float* __restrict__ wb,
    float* __restrict__ out,
    float (*ws)[BN * WPITCH], float (*xs)[BM * XPITCH],
    const int* sidx, int t, int m0, int n, int tile)
{
    const int mg = t & 3;
    const int cg = t >> 2;

    const int wrow = t >> 3;
    const int wq4  = (t & 7) * 4;
    const int xm0  = t >> 3;
    const int xq0  = (t & 7) * 4;
    const int xm1  = (t + NT) >> 3;
    const int xq1  = ((t + NT) & 7) * 4;
    const float* xr0 = x + (size_t)sidx[xm0] * IND + xq0;
    const float* xr1 = (RMAX == 8) ? (x + (size_t)sidx[xm1] * IND + xq1) : nullptr;

    unsigned long long acc[RMAX][4];
    #pragma unroll
    for (int r = 0; r < RMAX; r++)
        #pragma unroll
        for (int c = 0; c < 4; c++) acc[r][c] = 0ULL;

    // prologue: stage 0
    {
        float* wsb = ws[0];
        float* xsb = xs[0];
        #pragma unroll
        for (int p = 0; p < 8; p++) {
            int row = wrow + 16 * p;
            cp16(sm_addr(&wsb[row * WPITCH + wq4]), wb + (size_t)row * IND + wq4);
        }
        cp16(sm_addr(&xsb[xm0 * XPITCH + xq0]), xr0);
        if (RMAX == 8) cp16(sm_addr(&xsb[xm1 * XPITCH + xq1]), xr1);
        CP_COMMIT();
    }

    for (int s = 0; s < NSTAGE; s++) {
        if (s + 1 < NSTAGE) {
            int k0 = (s + 1) * BK;
            float* wsb = ws[(s + 1) & 1];
            float* xsb = xs[(s + 1) & 1];
            #pragma unroll
            for (int p = 0; p < 8; p++) {
                int row = wrow + 16 * p;
                cp16(sm_addr(&wsb[row * WPITCH + wq4]), wb + (size_t)row * IND + k0 + wq4);
            }
            cp16(sm_addr(&xsb[xm0 * XPITCH + xq0]), xr0 + k0);
            if (RMAX == 8) cp16(sm_addr(&xsb[xm1 * XPITCH + xq1]), xr1 + k0);
            CP_COMMIT();
            CP_WAIT1();
        } else {
            CP_WAIT0();
        }
        __syncthreads();

        const float* wsb = ws[s & 1];
        const float* xsb = xs[s & 1];
        #pragma unroll
        for (int kp = 0; kp < BK / 4; kp++) {
            ulonglong2 wv[4];
            #pragma unroll
            for (int c = 0; c < 4; c++)
                wv[c] = *(const ulonglong2*)&wsb[(cg + 32 * c) * WPITCH + kp * 4];
            #pragma unroll
            for (int r = 0; r < RMAX; r++) {
                ulonglong2 xv = *(const ulonglong2*)&xsb[(mg + 4 * r) * XPITCH + kp * 4];
                #pragma unroll
                for (int c = 0; c < 4; c++) {
                    fma2(acc[r][c], xv.x, wv[c].x);
                    fma2(acc[r][c], xv.y, wv[c].y);
                }
            }
        }
        __syncthreads();
    }

    // epilogue: merge k-halves, masked store
    #pragma unroll
    for (int r = 0; r < RMAX; r++) {
        int ml = mg + 4 * r;
        int m  = m0 + ml;
        if (m < n) {
            float* op = out + (size_t)sidx[ml] * OUTD + (size_t)tile * BN + cg;
            #pragma unroll
            for (int c = 0; c < 4; c++) {
                float lo = __uint_as_float((unsigned)(acc[r][c]));
                float hi = __uint_as_float((unsigned)(acc[r][c] >> 32));
                op[32 * c] = lo + hi;
            }
        }
    }
}

__global__ __launch_bounds__(NT, 3) void gemm_kernel(
    const float* __restrict__ x,
    const float* __restrict__ w,
    float* __restrict__ out)
{
    __shared__ float ws[2][BN * WPITCH];
    __shared__ float xs[2][BM * XPITCH];
    __shared__ int sidx[BM];

    const int it = blockIdx.x;
    if (it >= g_nitems) return;

    const int t    = threadIdx.x;
    const int pk   = g_items[it];
    const int e    = pk >> 16;
    const int tile = pk & 3;
    const int small = (pk >> 2) & 1;
    const int m0   = ((pk >> 4) & 0xfff) * 16;
    const int n    = g_count[e];
    const int* ls  = g_list + e * BQ;

    if (t < BM) {
        int m = m0 + t;
        sidx[t] = ls[m < n ? m : n - 1];
    }
    __syncthreads();

    const float* wb = w + ((size_t)e * OUTD + (size_t)tile * BN) * IND;

    if (small)
        run_item<4>(x, wb, out, ws, xs, sidx, t, m0, n, tile);
    else
        run_item<8>(x, wb, out, ws, xs, sidx, t, m0, n, tile);
}

extern "C" void kernel_launch(void* const* d_in, const int* in_sizes, int n_in,
                              void* d_out, int out_size) {
    const float* x = nullptr;
    const int* ids = nullptr;
    const float* w = nullptr;
    for (int i = 0; i < n_in; i++) {
        if (in_sizes[i] == BQ * IND)                x   = (const float*)d_in[i];
        else if (in_sizes[i] == BQ)                 ids = (const int*)d_in[i];
        else if (in_sizes[i] == NEXP * OUTD * IND)  w   = (const float*)d_in[i];
    }
    float* out = (float*)d_out;

    prep_kernel<<<1, 256>>>(ids);
    gemm_kernel<<<GRID_GEMM, NT>>>(x, w, out);
}

// round 13
// speedup vs baseline: 3.0157x; 1.5562x over previous
#include <cuda_runtime.h>
#include <cstdint>

#define BQ     2048
#define IND    512
#define OUTD   512
#define NEXP   64

#define MT     128            // M: W rows per item
#define NTILE  64             // N: samples per item
#define BK     32             // k per stage
#define NSTAGE (IND / BK)     // 16
#define NT     128            // 4 warps
#define GRID_GEMM 384         // worst case: sum ceil(n_e/64)*4 <= (64+32)*4
#define MAXITEMS 512

#define APITCH 36             // floats per A smem row
#define BPITCH 36
#define A_F    (MT * APITCH)       // 4608 floats
#define B_F    (NTILE * BPITCH)    // 2304 floats
#define SMEM_DYN ((2 * (A_F + B_F)) * 4)   // 55296 B

__device__ int g_count[NEXP];
__device__ int g_list[NEXP * BQ];
__device__ int g_items[MAXITEMS];
__device__ int g_nitems;

// ---------------- prep ----------------
__global__ void prep_kernel(const int* __restrict__ ids) {
    __shared__ int sc[NEXP];
    int t = threadIdx.x;
    if (t < NEXP) sc[t] = 0;
    __syncthreads();
    for (int i = t; i < BQ; i += blockDim.x) {
        int e = ids[i];
        if ((unsigned)e < NEXP) {
            int p = atomicAdd(&sc[e], 1);
            g_list[e * BQ + p] = i;
        }
    }
    __syncthreads();
    if (t < NEXP) g_count[t] = sc[t];
    if (t == 0) {
        int ni = 0;
        for (int e = 0; e < NEXP; e++) {
            int n = sc[e];
            for (int ch = 0; ch * NTILE < n && ni <= MAXITEMS - 4; ch++)
                for (int mt = 0; mt < 4; mt++)
                    g_items[ni++] = (e << 16) | (ch << 2) | mt;
        }
        g_nitems = ni;
    }
}

// ---------------- helpers ----------------
__device__ __forceinline__ uint4 cvt4_tf32(float4 v) {
    uint4 u;
    asm("cvt.rna.tf32.f32 %0, %1;" : "=r"(u.x) : "f"(v.x));
    asm("cvt.rna.tf32.f32 %0, %1;" : "=r"(u.y) : "f"(v.y));
    asm("cvt.rna.tf32.f32 %0, %1;" : "=r"(u.z) : "f"(v.z));
    asm("cvt.rna.tf32.f32 %0, %1;" : "=r"(u.w) : "f"(v.w));
    return u;
}
__device__ __forceinline__ void mma_tf32(float* d, const uint32_t* a,
                                         uint32_t b0, uint32_t b1) {
    asm volatile(
        "mma.sync.aligned.m16n8k8.row.col.f32.tf32.tf32.f32 "
        "{%0,%1,%2,%3}, {%4,%5,%6,%7}, {%8,%9}, {%0,%1,%2,%3};"
        : "+f"(d[0]), "+f"(d[1]), "+f"(d[2]), "+f"(d[3])
        : "r"(a[0]), "r"(a[1]), "r"(a[2]), "r"(a[3]), "r"(b0), "r"(b1));
}

// ---------------- grouped GEMM via mma.sync tf32 ----------------
// Item (e, ch, mt): D[128 W-rows, 64 samples] = W_tile · x_chunk^T.
// 4 warps; warp w owns M-rows [w*32, w*32+32). Per 8-k step: 16 mma m16n8k8.
__global__ __launch_bounds__(NT) void gemm_kernel(
    const float* __restrict__ x,
    const float* __restrict__ w,
    float* __restrict__ out)
{
    extern __shared__ uint32_t dsm[];
    uint32_t* Abuf[2] = { dsm,             dsm + A_F + B_F };
    uint32_t* Bbuf[2] = { dsm + A_F,       dsm + 2 * A_F + B_F };
    __shared__ int sidx[NTILE];

    const int it = blockIdx.x;
    if (it >= g_nitems) return;

    const int t    = threadIdx.x;
    const int wrp  = t >> 5;
    const int lane = t & 31;
    const int ly   = lane >> 2;   // group id
    const int lx   = lane & 3;    // thread-in-group
    const int rb   = wrp * 32;    // warp's M base

    const int pk = g_items[it];
    const int e  = pk >> 16;
    const int mt = pk & 3;
    const int ch = (pk >> 2) & 0x3fff;
    const int n  = g_count[e];
    const int nvalid = min(n - ch * NTILE, NTILE);
    const int* ls = g_list + e * BQ;

    if (t < NTILE) {
        int m = ch * NTILE + t;
        sidx[t] = ls[m < n ? m : n - 1];
    }
    __syncthreads();

    const float* wb = w + ((size_t)e * OUTD + (size_t)mt * MT) * IND;

    // fill mapping: unit = t + 128*j -> row = frow + 16*j, quad fq
    const int frow = t >> 3;
    const int fq4  = (t & 7) * 4;
    const float* xp[4];
    #pragma unroll
    for (int j = 0; j < 4; j++)
        xp[j] = x + (size_t)sidx[frow + 16 * j] * IND + fq4;

    float4 rw[8], rx[4];
    // ---- prefetch stage 0
    #pragma unroll
    for (int j = 0; j < 8; j++)
        rw[j] = *(const float4*)(wb + (size_t)(frow + 16 * j) * IND + fq4);
    #pragma unroll
    for (int j = 0; j < 4; j++)
        rx[j] = *(const float4*)(xp[j]);

    float acc[2][8][4];
    #pragma unroll
    for (int i = 0; i < 2; i++)
        #pragma unroll
        for (int j = 0; j < 8; j++)
            #pragma unroll
            for (int q = 0; q < 4; q++) acc[i][j][q] = 0.0f;

    for (int s = 0; s < NSTAGE; s++) {
        const int b = s & 1;
        uint32_t* Au = Abuf[b];
        uint32_t* Bu = Bbuf[b];

        // ---- STS stage s (cvt to tf32)
        #pragma unroll
        for (int j = 0; j < 8; j++)
            *(uint4*)&Au[(frow + 16 * j) * APITCH + fq4] = cvt4_tf32(rw[j]);
        #pragma unroll
        for (int j = 0; j < 4; j++)
            *(uint4*)&Bu[(frow + 16 * j) * BPITCH + fq4] = cvt4_tf32(rx[j]);
        __syncthreads();

        // ---- prefetch stage s+1 (overlaps mma below)
        if (s + 1 < NSTAGE) {
            int k0 = (s + 1) * BK;
            #pragma unroll
            for (int j = 0; j < 8; j++)
                rw[j] = *(const float4*)(wb + (size_t)(frow + 16 * j) * IND + k0 + fq4);
            #pragma unroll
            for (int j = 0; j < 4; j++)
                rx[j] = *(const float4*)(xp[j] + k0);
        }

        // ---- compute stage s: 4 ksteps x (2 m-tiles x 8 n-tiles) mma
        #pragma unroll
        for (int ks = 0; ks < 4; ks++) {
            const int k = ks * 8;
            uint32_t a[2][4];
            #pragma unroll
            for (int i = 0; i < 2; i++) {
                int r0 = rb + i * 16 + ly;
                a[i][0] = Au[r0 * APITCH + k + lx];
                a[i][1] = Au[(r0 + 8) * APITCH + k + lx];
                a[i][2] = Au[r0 * APITCH + k + lx + 4];
                a[i][3] = Au[(r0 + 8) * APITCH + k + lx + 4];
            }
            #pragma unroll
            for (int j = 0; j < 8; j++) {
                int nr = j * 8 + ly;
                uint32_t b0 = Bu[nr * BPITCH + k + lx];
                uint32_t b1 = Bu[nr * BPITCH + k + lx + 4];
                mma_tf32(acc[0][j], a[0], b0, b1);
                mma_tf32(acc[1][j], a[1], b0, b1);
            }
        }
        __syncthreads();   // all warps done reading buf b before it refills (s+2)
    }

    // ---- epilogue: C frag (i,j): rows rb+i*16+ly(+8), cols j*8+lx*2(+1)
    float* ob = out + (size_t)mt * MT;
    #pragma unroll
    for (int i = 0; i < 2; i++) {
        #pragma unroll
        for (int j = 0; j < 8; j++) {
            int r0 = rb + i * 16 + ly;
            int r1 = r0 + 8;
            int c0 = j * 8 + lx * 2;
            int c1 = c0 + 1;
            if (c0 < nvalid) {
                size_t s0 = (size_t)sidx[c0] * OUTD;
                ob[s0 + r0] = acc[i][j][0];
                ob[s0 + r1] = acc[i][j][2];
            }
            if (c1 < nvalid) {
                size_t s1 = (size_t)sidx[c1] * OUTD;
                ob[s1 + r0] = acc[i][j][1];
                ob[s1 + r1] = acc[i][j][3];
            }
        }
    }
}

extern "C" void kernel_launch(void* const* d_in, const int* in_sizes, int n_in,
                              void* d_out, int out_size) {
    const float* x = nullptr;
    const int* ids = nullptr;
    const float* w = nullptr;
    for (int i = 0; i < n_in; i++) {
        if (in_sizes[i] == BQ * IND)                x   = (const float*)d_in[i];
        else if (in_sizes[i] == BQ)                 ids = (const int*)d_in[i];
        else if (in_sizes[i] == NEXP * OUTD * IND)  w   = (const float*)d_in[i];
    }
    float* out = (float*)d_out;

    cudaFuncSetAttribute(gemm_kernel,
                         cudaFuncAttributeMaxDynamicSharedMemorySize, SMEM_DYN);

    prep_kernel<<<1, 256>>>(ids);
    gemm_kernel<<<GRID_GEMM, NT, SMEM_DYN>>>(x, w, out);
}